// round 15
// baseline (speedup 1.0000x reference)
#include <cuda_runtime.h>
#include <cuda_bf16.h>
#include <math.h>

#define BB 32
#define TT 256
#define EE 256
#define HHD 256
#define KK 12
#define TSTART 10
#define TSTOP 11
#define NEGV (-10000.0f)

// ------------------- static device scratch -------------------
__device__ float g_G2[2][TT][BB][1024];         // gate pre-activations [dir][t][b][jg], jg=g*256+u
__device__ float g_h[2][2][BB][HHD];            // h double buffer [parity][dir][b][u]
__device__ float g_Hcat[BB][TT][512];           // concatenated hidden states
__device__ float g_feats[BB][TT][KK];           // emission features
__device__ unsigned g_ctr[4][TT];               // per-(dir,grp) per-step arrival counters

// ------------------- init: zero counters, seed h0 -------------------
__global__ void k_init(const float* __restrict__ h0) {
    int i = blockIdx.x * blockDim.x + threadIdx.x;
    if (i < 4 * TT) ((unsigned*)g_ctr)[i] = 0u;
    if (i < 2 * BB * HHD) ((float*)g_h[0])[i] = h0[i];   // parity 0 = input for t=0
}

// ------------------- fused gather + input-projection GEMM -------------------
// g_G2[dir][t][b][jg] = emb[tok(t,b,dir)] . Wih[jg,:] + bih[jg] + bhh[jg]
#define GP 68
__global__ void k_gemm(const int* __restrict__ sent, const int* __restrict__ lens,
                       const float* __restrict__ emb,
                       const float* __restrict__ Wf, const float* __restrict__ Wb,
                       const float* __restrict__ bihf, const float* __restrict__ bhhf,
                       const float* __restrict__ bihb, const float* __restrict__ bhhb) {
    __shared__ __align__(16) float Xs[16][GP];
    __shared__ __align__(16) float Ws[16][GP];
    __shared__ int toks[64];
    int dir  = blockIdx.z;
    int row0 = blockIdx.y * 64;
    int j0   = blockIdx.x * 64;
    const float* W = dir ? Wb : Wf;
    int tid = threadIdx.x;             // 256
    int tx = tid & 15, ty = tid >> 4;
    int lk = tid & 15, lr = tid >> 4;

    if (tid < 64) {
        int row = row0 + tid;
        int t = row >> 5, b = row & 31;
        int len = lens[b];
        int pos = dir ? ((t < len) ? (len - 1 - t) : t) : t;
        toks[tid] = sent[b * TT + pos];
    }
    __syncthreads();
    int myrow[4];
#pragma unroll
    for (int it = 0; it < 4; it++) myrow[it] = toks[lr + it * 16];

    float acc[4][4];
#pragma unroll
    for (int i = 0; i < 4; i++)
#pragma unroll
        for (int j = 0; j < 4; j++) acc[i][j] = 0.f;

    for (int k0 = 0; k0 < 256; k0 += 16) {
        __syncthreads();
#pragma unroll
        for (int it = 0; it < 4; it++) {
            int r = lr + it * 16;
            Xs[lk][r] = emb[myrow[it] * EE + k0 + lk];
            Ws[lk][r] = W[(j0 + r) * EE + k0 + lk];
        }
        __syncthreads();
#pragma unroll
        for (int kk = 0; kk < 16; kk++) {
            float4 xa = *(const float4*)&Xs[kk][ty * 4];
            float4 wb = *(const float4*)&Ws[kk][tx * 4];
            float xr[4] = {xa.x, xa.y, xa.z, xa.w};
            float wr[4] = {wb.x, wb.y, wb.z, wb.w};
#pragma unroll
            for (int i = 0; i < 4; i++)
#pragma unroll
                for (int j = 0; j < 4; j++) acc[i][j] += xr[i] * wr[j];
        }
    }
    // epilogue: add biases (float4), coalesced STG.128 per row
    int jg0 = j0 + tx * 4;
    float4 bi = dir ? *(const float4*)&bihb[jg0] : *(const float4*)&bihf[jg0];
    float4 bh = dir ? *(const float4*)&bhhb[jg0] : *(const float4*)&bhhf[jg0];
    float4 bs = make_float4(bi.x + bh.x, bi.y + bh.y, bi.z + bh.z, bi.w + bh.w);
#pragma unroll
    for (int i = 0; i < 4; i++) {
        int row = row0 + ty * 4 + i;
        int t = row >> 5, b = row & 31;
        float4 v = make_float4(acc[i][0] + bs.x, acc[i][1] + bs.y,
                               acc[i][2] + bs.z, acc[i][3] + bs.w);
        *(float4*)&g_G2[dir][t][b][jg0] = v;
    }
}

// ------------------- persistent recurrent LSTM: 2 independent chains/block ----
// 128 blocks x 128 threads. Chain A = warps 0-1 (dir 0), chain B = warps 2-3 (dir 1).
// Each chain: 16 batches x 4 hidden units per thread-group of 64.
// Per-chain sync via named barriers; cross-block sync via per-group counters.
__device__ __forceinline__ float fsig(float x) { return 1.f / (1.f + __expf(-x)); }

__global__ void __launch_bounds__(128, 1)
k_lstm(const float* __restrict__ Whhf, const float* __restrict__ Whhb,
       const float* __restrict__ c0, const int* __restrict__ lens) {
    extern __shared__ __align__(16) float sm[];   // 64KB: ws[2][4096], hs[2][4096]

    int bid = blockIdx.x;
    int tid = threadIdx.x;              // 128
    int chain = tid >> 6;               // 0: warps 0-1, 1: warps 2-3
    int tc = tid & 63;
    int dir = chain;
    int grp = (bid >> 6) ^ chain;       // chains in one block belong to different sync groups
    int uslc = bid & 63;                // 64 u-slices of 4
    int u0 = uslc * 4;
    int sg = dir * 2 + grp;
    int u_l = tc & 3, b_l = tc >> 2;    // 4 u x 16 b
    int u = u0 + u_l;
    int b = grp * 16 + b_l;
    const float* Whh = dir ? Whhb : Whhf;
    float* ws = sm + chain * 4096;          // [v][u_l][gate]
    float* hs = sm + 8192 + chain * 4096;   // [b_l][v] XOR-swizzled

    // load Whh slice (16 rows): ws[v*16 + ul*4 + g] = Whh[(g*256 + u0 + ul)][v]
    for (int i = tc; i < 16 * 256; i += 64) {
        int v = i & 255;
        int r = i >> 8;                  // ul*4 + g
        int ul2 = r >> 2, g2 = r & 3;
        ws[v * 16 + ul2 * 4 + g2] = Whh[(g2 * 256 + u0 + ul2) * HHD + v];
    }
    float c = c0[(dir * BB + b) * HHD + u];
    int len = lens[b];
    int xsw = b_l & 7;
    const unsigned* myctr = &g_ctr[sg][0];
    int barid = 1 + chain;
    __syncthreads();   // both chains' weights staged

    for (int t = 0; t < TT; t++) {
        // prefetch gate pre-activations (independent of h)
        const float* gbase = &g_G2[dir][t][b][0];
        float gp0 = __ldg(gbase + u);
        float gp1 = __ldg(gbase + 256 + u);
        float gp2 = __ldg(gbase + 512 + u);
        float gp3 = __ldg(gbase + 768 + u);

        // wait for all 64 peer chain-slices to have produced step-t input
        if (t > 0 && tc == 0) {
            unsigned v;
            const unsigned* fp = myctr + (t - 1);
            do {
                asm volatile("ld.acquire.gpu.global.u32 %0, [%1];"
                             : "=r"(v) : "l"(fp) : "memory");
            } while (v < 64u);
        }
        asm volatile("bar.sync %0, 64;" :: "r"(barid) : "memory");

        // restage h (16 batches x 256) from L2, 8-way XOR swizzle (conflict-free)
        {
            const float4* src = (const float4*)&g_h[t & 1][dir][grp * 16][0];
            for (int i = tc; i < 1024; i += 64) {
                float4 hv = __ldcg(src + i);
                int bb2 = i >> 6, cc = i & 63;
                *(float4*)&hs[bb2 * 256 + ((cc ^ (bb2 & 7)) << 2)] = hv;
            }
        }
        asm volatile("bar.sync %0, 64;" :: "r"(barid) : "memory");

        // GEMV: 4 gates x 256
        float ai = 0.f, af = 0.f, ag = 0.f, ao = 0.f;
        const float* hrow = hs + b_l * 256;
#pragma unroll 8
        for (int v = 0; v < 256; v += 4) {
            float4 h4 = *(const float4*)&hrow[((v >> 2) ^ xsw) << 2];
            float4 w0 = *(const float4*)&ws[(v + 0) * 16 + u_l * 4];
            float4 w1 = *(const float4*)&ws[(v + 1) * 16 + u_l * 4];
            float4 w2 = *(const float4*)&ws[(v + 2) * 16 + u_l * 4];
            float4 w3 = *(const float4*)&ws[(v + 3) * 16 + u_l * 4];
            ai += w0.x * h4.x; af += w0.y * h4.x; ag += w0.z * h4.x; ao += w0.w * h4.x;
            ai += w1.x * h4.y; af += w1.y * h4.y; ag += w1.z * h4.y; ao += w1.w * h4.y;
            ai += w2.x * h4.z; af += w2.y * h4.z; ag += w2.z * h4.z; ao += w2.w * h4.z;
            ai += w3.x * h4.w; af += w3.y * h4.w; ag += w3.z * h4.w; ao += w3.w * h4.w;
        }
        ai += gp0; af += gp1; ag += gp2; ao += gp3;
        float ig = fsig(ai), fg = fsig(af), gg = tanhf(ag), og = fsig(ao);
        c = fg * c + ig * gg;
        float h = og * tanhf(c);

        __stcg(&g_h[(t + 1) & 1][dir][b][u], h);
        int pos = dir ? ((t < len) ? (len - 1 - t) : t) : t;
        g_Hcat[b][pos][dir * 256 + u] = h;

        asm volatile("bar.sync %0, 64;" :: "r"(barid) : "memory");  // chain stores done
        if (tc == 0) {
            asm volatile("red.release.gpu.global.add.u32 [%0], %1;"
                         :: "l"(myctr + t), "r"(1u) : "memory");
        }
    }
}

// ------------------- emission features: Hcat @ W_out^T + b_out -------------------
__global__ void k_feats(const float* __restrict__ Wout, const float* __restrict__ bout) {
    __shared__ __align__(16) float Wsh[12 * 516];
    __shared__ __align__(16) float Hsh[8 * 516];
    int blk = blockIdx.x;              // 1024 blocks, 8 rows each
    int tid = threadIdx.x;             // 128
    for (int i = tid; i < 12 * 512; i += 128) Wsh[(i >> 9) * 516 + (i & 511)] = Wout[i];
    int row0 = blk * 8;                // row = b*256 + t
    for (int i = tid; i < 8 * 512; i += 128)
        Hsh[(i >> 9) * 516 + (i & 511)] = ((const float*)g_Hcat)[(row0 + (i >> 9)) * 512 + (i & 511)];
    __syncthreads();
    if (tid < 96) {
        int rl = tid / 12, k = tid % 12;
        float s0 = bout[k], s1 = 0.f, s2 = 0.f, s3 = 0.f;
        const float* wr = &Wsh[k * 516];
        const float* hr = &Hsh[rl * 516];
#pragma unroll 8
        for (int hh = 0; hh < 512; hh += 4) {
            float4 a = *(const float4*)&wr[hh];
            float4 bb4 = *(const float4*)&hr[hh];
            s0 += a.x * bb4.x; s1 += a.y * bb4.y; s2 += a.z * bb4.z; s3 += a.w * bb4.w;
        }
        ((float*)g_feats)[(row0 + rl) * 12 + k] = (s0 + s1) + (s2 + s3);
    }
}

// ------------------- Viterbi DP + backtrace -------------------
__global__ void k_viterbi(const float* __restrict__ trans, const int* __restrict__ lens,
                          float* __restrict__ out) {
    __shared__ float tr[144];
    __shared__ float fv[8][13];
    __shared__ unsigned char bp[TT][8][12];
    __shared__ int lsh[8];
    int b0 = blockIdx.x * 8;
    int tid = threadIdx.x;             // 128
    for (int i = tid; i < 144; i += 128) tr[i] = trans[i];
    if (tid < 8) lsh[tid] = lens[b0 + tid];
    int rl = tid / 12, k = tid % 12;
    bool act = tid < 96;
    if (act) fv[rl][k] = (k == TSTART) ? 0.f : NEGV;
    __syncthreads();

    float trk[12];
    if (act) {
#pragma unroll
        for (int p = 0; p < 12; p++) trk[p] = tr[k * 12 + p];
    }
    int len = act ? lsh[rl] : 0;
    int bg = b0 + rl;

    for (int t = 0; t < TT; t++) {
        float nf = 0.f;
        if (act) {
            float feat = ((const float*)g_feats)[(bg * TT + t) * 12 + k];
            float best = fv[rl][0] + trk[0];
            int bpi = 0;
#pragma unroll
            for (int p = 1; p < 12; p++) {
                float s = fv[rl][p] + trk[p];
                if (s > best) { best = s; bpi = p; }   // strict > => first max (jnp.argmax)
            }
            bp[t][rl][k] = (unsigned char)bpi;
            nf = (t < len) ? (best + feat) : fv[rl][k];
        }
        __syncthreads();
        if (act) fv[rl][k] = nf;
        __syncthreads();
    }

    if (tid < 8) {
        int r = tid;
        int bgl = b0 + r;
        int ln = lsh[r];
        float best = fv[r][0] + tr[TSTOP * 12 + 0];
        int tag = 0;
        for (int p = 1; p < 12; p++) {
            float s = fv[r][p] + tr[TSTOP * 12 + p];
            if (s > best) { best = s; tag = p; }
        }
        out[bgl] = best;                               // path score
        for (int t = TT - 1; t >= 0; t--) {
            bool m = t < ln;
            out[BB + bgl * TT + t] = m ? (float)tag : -1.0f;
            if (m) tag = bp[t][r][tag];
        }
    }
}

// ------------------- launch -------------------
extern "C" void kernel_launch(void* const* d_in, const int* in_sizes, int n_in,
                              void* d_out, int out_size) {
    const int*   sent  = (const int*)d_in[0];
    const int*   lens  = (const int*)d_in[1];
    const float* emb   = (const float*)d_in[2];
    const float* Wihf  = (const float*)d_in[3];
    const float* Whhf  = (const float*)d_in[4];
    const float* bihf  = (const float*)d_in[5];
    const float* bhhf  = (const float*)d_in[6];
    const float* Wihb  = (const float*)d_in[7];
    const float* Whhb  = (const float*)d_in[8];
    const float* bihb  = (const float*)d_in[9];
    const float* bhhb  = (const float*)d_in[10];
    const float* h0    = (const float*)d_in[11];
    const float* c0    = (const float*)d_in[12];
    const float* Wout  = (const float*)d_in[13];
    const float* bout  = (const float*)d_in[14];
    const float* trans = (const float*)d_in[15];
    float* out = (float*)d_out;

    static int smem_set = 0;
    if (!smem_set) {
        cudaFuncSetAttribute(k_lstm, cudaFuncAttributeMaxDynamicSharedMemorySize, 65536);
        smem_set = 1;
    }

    k_init<<<64, 256>>>(h0);
    dim3 gg(16, 128, 2);
    k_gemm<<<gg, 256>>>(sent, lens, emb, Wihf, Wihb, bihf, bhhf, bihb, bhhb);
    k_lstm<<<128, 128, 65536>>>(Whhf, Whhb, c0, lens);
    k_feats<<<1024, 128>>>(Wout, bout);
    k_viterbi<<<4, 128>>>(trans, lens, out);
}

// round 16
// speedup vs baseline: 1.4927x; 1.4927x over previous
#include <cuda_runtime.h>
#include <cuda_bf16.h>
#include <math.h>

#define BB 32
#define TT 256
#define EE 256
#define HHD 256
#define KK 12
#define TSTART 10
#define TSTOP 11
#define NEGV (-10000.0f)

// ------------------- static device scratch -------------------
__device__ float g_G2[2][TT][BB][1024];         // gate pre-activations [dir][t][b][jg], jg=g*256+u
__device__ float g_h[2][2][BB][HHD];            // h double buffer [parity][dir][b][u]
__device__ float g_Hcat[BB][TT][512];           // concatenated hidden states
__device__ float g_feats[BB][TT][KK];           // emission features
__device__ unsigned g_ctr[4][TT];               // per-(dir,grp) per-step arrival counters

// ------------------- init: zero counters, seed h0 -------------------
__global__ void k_init(const float* __restrict__ h0) {
    int i = blockIdx.x * blockDim.x + threadIdx.x;
    if (i < 4 * TT) ((unsigned*)g_ctr)[i] = 0u;
    if (i < 2 * BB * HHD) ((float*)g_h[0])[i] = h0[i];   // parity 0 = input for t=0
}

// ------------------- fused gather + input-projection GEMM -------------------
// g_G2[dir][t][b][jg] = emb[tok(t,b,dir)] . Wih[jg,:] + bih[jg] + bhh[jg]
#define GP 68
__global__ void k_gemm(const int* __restrict__ sent, const int* __restrict__ lens,
                       const float* __restrict__ emb,
                       const float* __restrict__ Wf, const float* __restrict__ Wb,
                       const float* __restrict__ bihf, const float* __restrict__ bhhf,
                       const float* __restrict__ bihb, const float* __restrict__ bhhb) {
    __shared__ __align__(16) float Xs[16][GP];
    __shared__ __align__(16) float Ws[16][GP];
    __shared__ int toks[64];
    int dir  = blockIdx.z;
    int row0 = blockIdx.y * 64;
    int j0   = blockIdx.x * 64;
    const float* W = dir ? Wb : Wf;
    int tid = threadIdx.x;             // 256
    int tx = tid & 15, ty = tid >> 4;
    int lk = tid & 15, lr = tid >> 4;

    if (tid < 64) {
        int row = row0 + tid;
        int t = row >> 5, b = row & 31;
        int len = lens[b];
        int pos = dir ? ((t < len) ? (len - 1 - t) : t) : t;
        toks[tid] = sent[b * TT + pos];
    }
    __syncthreads();
    int myrow[4];
#pragma unroll
    for (int it = 0; it < 4; it++) myrow[it] = toks[lr + it * 16];

    float acc[4][4];
#pragma unroll
    for (int i = 0; i < 4; i++)
#pragma unroll
        for (int j = 0; j < 4; j++) acc[i][j] = 0.f;

    for (int k0 = 0; k0 < 256; k0 += 16) {
        __syncthreads();
#pragma unroll
        for (int it = 0; it < 4; it++) {
            int r = lr + it * 16;
            Xs[lk][r] = emb[myrow[it] * EE + k0 + lk];
            Ws[lk][r] = W[(j0 + r) * EE + k0 + lk];
        }
        __syncthreads();
#pragma unroll
        for (int kk = 0; kk < 16; kk++) {
            float4 xa = *(const float4*)&Xs[kk][ty * 4];
            float4 wb = *(const float4*)&Ws[kk][tx * 4];
            float xr[4] = {xa.x, xa.y, xa.z, xa.w};
            float wr[4] = {wb.x, wb.y, wb.z, wb.w};
#pragma unroll
            for (int i = 0; i < 4; i++)
#pragma unroll
                for (int j = 0; j < 4; j++) acc[i][j] += xr[i] * wr[j];
        }
    }
    // epilogue: add biases (float4), coalesced STG.128 per row
    int jg0 = j0 + tx * 4;
    float4 bi = dir ? *(const float4*)&bihb[jg0] : *(const float4*)&bihf[jg0];
    float4 bh = dir ? *(const float4*)&bhhb[jg0] : *(const float4*)&bhhf[jg0];
    float4 bs = make_float4(bi.x + bh.x, bi.y + bh.y, bi.z + bh.z, bi.w + bh.w);
#pragma unroll
    for (int i = 0; i < 4; i++) {
        int row = row0 + ty * 4 + i;
        int t = row >> 5, b = row & 31;
        float4 v = make_float4(acc[i][0] + bs.x, acc[i][1] + bs.y,
                               acc[i][2] + bs.z, acc[i][3] + bs.w);
        *(float4*)&g_G2[dir][t][b][jg0] = v;
    }
}

// ------------------- persistent recurrent LSTM (R13 structure, direct-L2 h) --
__device__ __forceinline__ float fsig(float x) { return 1.f / (1.f + __expf(-x)); }

__global__ void __launch_bounds__(128, 1)
k_lstm(const float* __restrict__ Whhf, const float* __restrict__ Whhb,
       const float* __restrict__ c0, const int* __restrict__ lens) {
    // static shared: 32KB weights only (no h staging)
    __shared__ __align__(16) float w_sh[256 * 32];   // [v][u_l][gate]

    int bid  = blockIdx.x;
    int dir  = bid >> 6;
    int grp  = (bid >> 5) & 1;
    int grp4 = bid >> 5;               // 0..3 sync group (dir,grp)
    int uslc = bid & 31;
    int tid  = threadIdx.x;            // 128
    int u_l  = tid & 7, b_l = tid >> 3;
    int u = uslc * 8 + u_l;
    int b = grp * 16 + b_l;
    const float* Whh = dir ? Whhb : Whhf;

    // load Whh slice (32 rows): w_sh[v*32 + ul*4 + g] = Whh[(g*256 + uslc*8 + ul)][v]
    for (int i = tid; i < 32 * 256; i += 128) {
        int v = i & 255;
        int ug = i >> 8;                 // ul*4 + g
        int ul2 = ug >> 2, g2 = ug & 3;
        w_sh[v * 32 + ul2 * 4 + g2] = Whh[(g2 * 256 + uslc * 8 + ul2) * HHD + v];
    }
    float c = c0[(dir * BB + b) * HHD + u];
    int len = lens[b];
    const float4* w4 = (const float4*)w_sh;
    const unsigned* myctr = &g_ctr[grp4][0];
    __syncthreads();

    for (int t = 0; t < TT; t++) {
        // prefetch gate pre-activations (independent of h)
        const float* gbase = &g_G2[dir][t][b][0];
        float gp0 = __ldg(gbase + u);
        float gp1 = __ldg(gbase + 256 + u);
        float gp2 = __ldg(gbase + 512 + u);
        float gp3 = __ldg(gbase + 768 + u);

        // wait for all 32 peer blocks to have produced step-t input
        if (t > 0 && tid == 0) {
            unsigned v;
            const unsigned* fp = myctr + (t - 1);
            do {
                asm volatile("ld.acquire.gpu.global.u32 %0, [%1];"
                             : "=r"(v) : "l"(fp) : "memory");
            } while (v < 32u);
        }
        __syncthreads();

        // GEMV: 4 gates x 256, h streamed directly from L2 (latency hidden by MLP+FMA)
        float ai = 0.f, af = 0.f, ag = 0.f, ao = 0.f;
        const float4* hsrc = (const float4*)&g_h[t & 1][dir][b][0];
#pragma unroll 8
        for (int v = 0; v < 256; v += 4) {
            float4 h4 = __ldcg(hsrc + (v >> 2));
            float4 w0 = w4[(v + 0) * 8 + u_l];
            float4 w1 = w4[(v + 1) * 8 + u_l];
            float4 w2 = w4[(v + 2) * 8 + u_l];
            float4 w3 = w4[(v + 3) * 8 + u_l];
            ai += w0.x * h4.x; af += w0.y * h4.x; ag += w0.z * h4.x; ao += w0.w * h4.x;
            ai += w1.x * h4.y; af += w1.y * h4.y; ag += w1.z * h4.y; ao += w1.w * h4.y;
            ai += w2.x * h4.z; af += w2.y * h4.z; ag += w2.z * h4.z; ao += w2.w * h4.z;
            ai += w3.x * h4.w; af += w3.y * h4.w; ag += w3.z * h4.w; ao += w3.w * h4.w;
        }
        ai += gp0; af += gp1; ag += gp2; ao += gp3;
        float ig = fsig(ai), fg = fsig(af), gg = tanhf(ag), og = fsig(ao);
        c = fg * c + ig * gg;
        float h = og * tanhf(c);

        __stcg(&g_h[(t + 1) & 1][dir][b][u], h);
        int pos = dir ? ((t < len) ? (len - 1 - t) : t) : t;
        g_Hcat[b][pos][dir * 256 + u] = h;

        __syncthreads();   // all CTA h-stores issued (program order before release)
        if (tid == 0) {
            asm volatile("red.release.gpu.global.add.u32 [%0], %1;"
                         :: "l"(myctr + t), "r"(1u) : "memory");
        }
    }
}

// ------------------- emission features: Hcat @ W_out^T + b_out -------------------
__global__ void k_feats(const float* __restrict__ Wout, const float* __restrict__ bout) {
    __shared__ __align__(16) float Wsh[12 * 516];
    __shared__ __align__(16) float Hsh[8 * 516];
    int blk = blockIdx.x;              // 1024 blocks, 8 rows each
    int tid = threadIdx.x;             // 128
    for (int i = tid; i < 12 * 512; i += 128) Wsh[(i >> 9) * 516 + (i & 511)] = Wout[i];
    int row0 = blk * 8;                // row = b*256 + t
    for (int i = tid; i < 8 * 512; i += 128)
        Hsh[(i >> 9) * 516 + (i & 511)] = ((const float*)g_Hcat)[(row0 + (i >> 9)) * 512 + (i & 511)];
    __syncthreads();
    if (tid < 96) {
        int rl = tid / 12, k = tid % 12;
        float s0 = bout[k], s1 = 0.f, s2 = 0.f, s3 = 0.f;
        const float* wr = &Wsh[k * 516];
        const float* hr = &Hsh[rl * 516];
#pragma unroll 8
        for (int hh = 0; hh < 512; hh += 4) {
            float4 a = *(const float4*)&wr[hh];
            float4 bb4 = *(const float4*)&hr[hh];
            s0 += a.x * bb4.x; s1 += a.y * bb4.y; s2 += a.z * bb4.z; s3 += a.w * bb4.w;
        }
        ((float*)g_feats)[(row0 + rl) * 12 + k] = (s0 + s1) + (s2 + s3);
    }
}

// ------------------- Viterbi DP + backtrace -------------------
__global__ void k_viterbi(const float* __restrict__ trans, const int* __restrict__ lens,
                          float* __restrict__ out) {
    __shared__ float tr[144];
    __shared__ float fv[8][13];
    __shared__ unsigned char bp[TT][8][12];
    __shared__ int lsh[8];
    int b0 = blockIdx.x * 8;
    int tid = threadIdx.x;             // 128
    for (int i = tid; i < 144; i += 128) tr[i] = trans[i];
    if (tid < 8) lsh[tid] = lens[b0 + tid];
    int rl = tid / 12, k = tid % 12;
    bool act = tid < 96;
    if (act) fv[rl][k] = (k == TSTART) ? 0.f : NEGV;
    __syncthreads();

    float trk[12];
    if (act) {
#pragma unroll
        for (int p = 0; p < 12; p++) trk[p] = tr[k * 12 + p];
    }
    int len = act ? lsh[rl] : 0;
    int bg = b0 + rl;

    for (int t = 0; t < TT; t++) {
        float nf = 0.f;
        if (act) {
            float feat = ((const float*)g_feats)[(bg * TT + t) * 12 + k];
            float best = fv[rl][0] + trk[0];
            int bpi = 0;
#pragma unroll
            for (int p = 1; p < 12; p++) {
                float s = fv[rl][p] + trk[p];
                if (s > best) { best = s; bpi = p; }   // strict > => first max (jnp.argmax)
            }
            bp[t][rl][k] = (unsigned char)bpi;
            nf = (t < len) ? (best + feat) : fv[rl][k];
        }
        __syncthreads();
        if (act) fv[rl][k] = nf;
        __syncthreads();
    }

    if (tid < 8) {
        int r = tid;
        int bgl = b0 + r;
        int ln = lsh[r];
        float best = fv[r][0] + tr[TSTOP * 12 + 0];
        int tag = 0;
        for (int p = 1; p < 12; p++) {
            float s = fv[r][p] + tr[TSTOP * 12 + p];
            if (s > best) { best = s; tag = p; }
        }
        out[bgl] = best;                               // path score
        for (int t = TT - 1; t >= 0; t--) {
            bool m = t < ln;
            out[BB + bgl * TT + t] = m ? (float)tag : -1.0f;
            if (m) tag = bp[t][r][tag];
        }
    }
}

// ------------------- launch -------------------
extern "C" void kernel_launch(void* const* d_in, const int* in_sizes, int n_in,
                              void* d_out, int out_size) {
    const int*   sent  = (const int*)d_in[0];
    const int*   lens  = (const int*)d_in[1];
    const float* emb   = (const float*)d_in[2];
    const float* Wihf  = (const float*)d_in[3];
    const float* Whhf  = (const float*)d_in[4];
    const float* bihf  = (const float*)d_in[5];
    const float* bhhf  = (const float*)d_in[6];
    const float* Wihb  = (const float*)d_in[7];
    const float* Whhb  = (const float*)d_in[8];
    const float* bihb  = (const float*)d_in[9];
    const float* bhhb  = (const float*)d_in[10];
    const float* h0    = (const float*)d_in[11];
    const float* c0    = (const float*)d_in[12];
    const float* Wout  = (const float*)d_in[13];
    const float* bout  = (const float*)d_in[14];
    const float* trans = (const float*)d_in[15];
    float* out = (float*)d_out;

    k_init<<<64, 256>>>(h0);
    dim3 gg(16, 128, 2);
    k_gemm<<<gg, 256>>>(sent, lens, emb, Wihf, Wihb, bihf, bhhf, bihb, bhhb);
    k_lstm<<<128, 128>>>(Whhf, Whhb, c0, lens);
    k_feats<<<1024, 128>>>(Wout, bout);
    k_viterbi<<<4, 128>>>(trans, lens, out);
}